// round 3
// baseline (speedup 1.0000x reference)
#include <cuda_runtime.h>
#include <cstddef>

#define Bn     4
#define Cn     64
#define Hn     512
#define Wn     512
#define NSPIX  256
#define HW     (Hn*Wn)

typedef unsigned long long ull;

// scratch
__device__ float g_spix [Bn*NSPIX*Cn];
__device__ float g_numer[Bn*NSPIX*Cn];
__device__ float g_denom2[2][Bn*NSPIX];

// ---- packed fp32x2 helpers ----
__device__ __forceinline__ ull f2_pack(float a, float b) {
    ull r; asm("mov.b64 %0, {%1,%2};" : "=l"(r) : "f"(a), "f"(b)); return r;
}
__device__ __forceinline__ void f2_unpack(ull v, float& a, float& b) {
    asm("mov.b64 {%0,%1}, %2;" : "=f"(a), "=f"(b) : "l"(v));
}
__device__ __forceinline__ void ffma2(ull& d, ull a, ull b) {
    asm("fma.rn.f32x2 %0, %1, %2, %0;" : "+l"(d) : "l"(a), "l"(b));
}

// shared layout (float offsets)
#define OFF_G    0                      // [9][64]
#define OFF_GSQ  576                    // [16]
#define OFF_DRED 592                    // [9][8]
#define OFF_M    664                    // [9][64]
#define OFF_W    1240                   // [256][20] dup (w,w) pairs, 16B-aligned rows
#define OFF_F    6360                   // [32 cpair][259 words] * 2 floats
#define SMEM_FLOATS (6360 + 32*259*2)   // 22936 floats = 91.7KB
#define SMEM_BYTES  (SMEM_FLOATS*4)
#define FWORD(cp,p) (OFF_F + ((cp)*259 + (p))*2)

// ---------------------------------------------------------------------------
__global__ void init_kernel(const float* __restrict__ f)
{
    __shared__ float sm[256];
    const int s = blockIdx.x, b = blockIdx.y;
    const int tid = threadIdx.x;
    const int c = tid & 63, part = tid >> 6;
    const int R = s >> 4, Cc = s & 15;
    const int y0 = R*32 + part*8, x0 = Cc*32;
    const float* fp = f + ((size_t)(b*Cn + c))*HW + (size_t)y0*Wn + x0;

    float sum = 0.f;
    for (int yy = 0; yy < 8; yy++) {
        const float4* r = (const float4*)(fp + (size_t)yy*Wn);
        #pragma unroll
        for (int x4 = 0; x4 < 8; x4++) {
            float4 v = r[x4];
            sum += (v.x + v.y) + (v.z + v.w);
        }
    }
    sm[tid] = sum;

    int gid = ((blockIdx.y*gridDim.x) + blockIdx.x)*256 + tid;
    if (gid < Bn*NSPIX*Cn) g_numer[gid] = 0.f;
    if (gid < 2*Bn*NSPIX)  ((float*)g_denom2)[gid] = 0.f;

    __syncthreads();
    if (tid < 64) {
        float t = sm[tid] + sm[64+tid] + sm[128+tid] + sm[192+tid];
        g_spix[(b*NSPIX + s)*Cn + tid] = t * (1.0f/1024.0f);
    }
}

// ---------------------------------------------------------------------------
// fused iteration kernel.  grid=(4,256,4)  block=256 (8x32 pixel tile)
// ---------------------------------------------------------------------------
__global__ __launch_bounds__(256, 2)
void ssn_iter_kernel(const float* __restrict__ f,
                     float* __restrict__ out_labels,
                     int it, int last)
{
    extern __shared__ float sm[];
    const int tid = threadIdx.x;
    const int bb = blockIdx.z, cell = blockIdx.y, q = blockIdx.x;
    const int R = cell >> 4, Cc = cell & 15;
    const int y0 = R*32 + q*8, x0 = Cc*32;
    const int par = it & 1;

    int  nbr[9];
    bool valid[9];
    #pragma unroll
    for (int k = 0; k < 9; k++) {
        int rr = R + k/3 - 1, cc = Cc + (k%3) - 1;
        bool v = (rr >= 0) & (rr < 16) & (cc >= 0) & (cc < 16);
        valid[k] = v;
        nbr[k]   = v ? rr*16 + cc : 0;
    }

    // stage g (zero-filled invalid), zero M + dred
    for (int idx = tid; idx < 576; idx += 256) {
        int k = idx >> 6;
        sm[OFF_G + idx] = valid[k] ? g_spix[(bb*NSPIX + nbr[k])*Cn + (idx & 63)] : 0.f;
        sm[OFF_M + idx] = 0.f;
    }
    if (tid < 72) sm[OFF_DRED + tid] = 0.f;
    __syncthreads();

    if (tid < 9) {                       // ||g||^2
        float s = 0.f;
        #pragma unroll 8
        for (int c = 0; c < 64; c++) { float gv = sm[OFF_G + tid*64 + c]; s += gv*gv; }
        sm[OFF_GSQ + tid] = s;
    }

    // ---- fused: stream f from HBM; stage to smem; accumulate 9 dots + ||f||^2
    const int p = tid;
    ull acc[9], sv = 0ull;
    #pragma unroll
    for (int k = 0; k < 9; k++) acc[k] = 0ull;
    {
        const float* fp = f + ((size_t)bb*Cn)*HW
                            + (size_t)(y0 + (p >> 5))*Wn + (x0 + (p & 31));
        #pragma unroll 4
        for (int cs = 0; cs < 16; cs++) {
            const int c = cs*4;
            float v0 = fp[(size_t)(c+0)*HW];
            float v1 = fp[(size_t)(c+1)*HW];
            float v2 = fp[(size_t)(c+2)*HW];
            float v3 = fp[(size_t)(c+3)*HW];
            ull p01 = f2_pack(v0, v1);
            ull p23 = f2_pack(v2, v3);
            *(ull*)&sm[FWORD((c>>1),   p)] = p01;
            *(ull*)&sm[FWORD((c>>1)+1, p)] = p23;
            ffma2(sv, p01, p01);
            ffma2(sv, p23, p23);
            #pragma unroll
            for (int k = 0; k < 9; k++) {
                ulonglong2 g2 = *(const ulonglong2*)&sm[OFF_G + k*64 + c];
                ffma2(acc[k], p01, g2.x);
                ffma2(acc[k], p23, g2.y);
            }
        }
    }
    __syncthreads();   // gsq ready; f tile complete (for phase 2 after next sync)

    // ---- softmax per pixel (registers)
    float w[9];
    {
        float sa, sb; f2_unpack(sv, sa, sb);
        const float sv_s = sa + sb;
        float dmin = 3.0e38f;
        #pragma unroll
        for (int k = 0; k < 9; k++) {
            float a, b; f2_unpack(acc[k], a, b);
            float d = valid[k] ? (sv_s - 2.f*(a+b) + sm[OFF_GSQ + k]) : 3.0e38f;
            w[k] = d;
            dmin = fminf(dmin, d);
        }
        if (last) {
            int kb = 0; float bd = w[0];
            #pragma unroll
            for (int k = 1; k < 9; k++) if (w[k] < bd) { bd = w[k]; kb = k; }
            out_labels[(size_t)bb*HW + (size_t)(y0 + (p>>5))*Wn + (x0 + (p&31))]
                = (float)nbr[kb];
        }
        float s = 0.f;
        #pragma unroll
        for (int k = 0; k < 9; k++) { float e = __expf(dmin - w[k]); w[k] = e; s += e; }
        float inv = 1.f / s;
        #pragma unroll
        for (int k = 0; k < 9; k++) w[k] *= inv;
    }

    // store duplicated (w,w) pairs for phase-2 FFMA2
    {
        float* wrow = &sm[OFF_W + p*20];
        #pragma unroll
        for (int k2 = 0; k2 < 4; k2++) {
            ulonglong2 t2;
            t2.x = f2_pack(w[2*k2],   w[2*k2]);
            t2.y = f2_pack(w[2*k2+1], w[2*k2+1]);
            *(ulonglong2*)&wrow[4*k2] = t2;
        }
        *(ull*)&wrow[16] = f2_pack(w[8], w[8]);
    }

    // denominators: 9 block-wide sums
    #pragma unroll
    for (int k = 0; k < 9; k++) {
        float s = w[k];
        s += __shfl_down_sync(0xffffffffu, s, 16);
        s += __shfl_down_sync(0xffffffffu, s, 8);
        s += __shfl_down_sync(0xffffffffu, s, 4);
        s += __shfl_down_sync(0xffffffffu, s, 2);
        s += __shfl_down_sync(0xffffffffu, s, 1);
        if ((tid & 31) == 0) sm[OFF_DRED + k*8 + (tid >> 5)] = s;
    }
    __syncthreads();   // w + dred visible
    if (tid < 9 && valid[tid]) {
        const float* dr = &sm[OFF_DRED + tid*8];
        float s = ((dr[0]+dr[1]) + (dr[2]+dr[3])) + ((dr[4]+dr[5]) + (dr[6]+dr[7]));
        atomicAdd(&g_denom2[par][bb*NSPIX + nbr[tid]], s);
    }

    // ---- phase 2: M[k][c] = sum_p w[k][p] f[c][p], channel-pair packed
    {
        const int cp  = tid & 15;        // owns cpairs cp, cp+16
        const int grp = tid >> 4;        // owns pixels grp*16 .. +16
        ull m[18];
        #pragma unroll
        for (int k = 0; k < 18; k++) m[k] = 0ull;
        #pragma unroll 2
        for (int j = 0; j < 16; j++) {
            const int pp = grp*16 + j;
            ull f0 = *(const ull*)&sm[FWORD(cp,      pp)];
            ull f1 = *(const ull*)&sm[FWORD(cp + 16, pp)];
            const float* wrow = &sm[OFF_W + pp*20];
            ulonglong2 wA = *(const ulonglong2*)&wrow[0];
            ulonglong2 wB = *(const ulonglong2*)&wrow[4];
            ulonglong2 wC = *(const ulonglong2*)&wrow[8];
            ulonglong2 wD = *(const ulonglong2*)&wrow[12];
            ull        wE = *(const ull*)&wrow[16];
            ffma2(m[0], wA.x, f0);  ffma2(m[ 9], wA.x, f1);
            ffma2(m[1], wA.y, f0);  ffma2(m[10], wA.y, f1);
            ffma2(m[2], wB.x, f0);  ffma2(m[11], wB.x, f1);
            ffma2(m[3], wB.y, f0);  ffma2(m[12], wB.y, f1);
            ffma2(m[4], wC.x, f0);  ffma2(m[13], wC.x, f1);
            ffma2(m[5], wC.y, f0);  ffma2(m[14], wC.y, f1);
            ffma2(m[6], wD.x, f0);  ffma2(m[15], wD.x, f1);
            ffma2(m[7], wD.y, f0);  ffma2(m[16], wD.y, f1);
            ffma2(m[8], wE,   f0);  ffma2(m[17], wE,   f1);
        }
        #pragma unroll
        for (int k = 0; k < 9; k++) {
            float a, b;
            f2_unpack(m[k], a, b);
            atomicAdd(&sm[OFF_M + k*64 + 2*cp],      a);
            atomicAdd(&sm[OFF_M + k*64 + 2*cp + 1],  b);
            f2_unpack(m[k+9], a, b);
            atomicAdd(&sm[OFF_M + k*64 + 2*cp + 32], a);
            atomicAdd(&sm[OFF_M + k*64 + 2*cp + 33], b);
        }
    }
    __syncthreads();

    // flush numerators
    for (int idx = tid; idx < 576; idx += 256) {
        int k = idx >> 6;
        if (valid[k])
            atomicAdd(&g_numer[(bb*NSPIX + nbr[k])*Cn + (idx & 63)], sm[OFF_M + idx]);
    }
}

// ---------------------------------------------------------------------------
__global__ void update_kernel(float* __restrict__ out_spix, int it, int last)
{
    int idx = blockIdx.x*256 + threadIdx.x;     // 65536
    int par = it & 1;
    float val = g_numer[idx] / (g_denom2[par][idx >> 6] + 1e-16f);
    g_spix[idx] = val;
    if (last) out_spix[idx] = val;
    g_numer[idx] = 0.f;
    if (idx < Bn*NSPIX) g_denom2[1 - par][idx] = 0.f;
}

// ---------------------------------------------------------------------------
extern "C" void kernel_launch(void* const* d_in, const int* in_sizes, int n_in,
                              void* d_out, int out_size)
{
    const float* f = (const float*)d_in[0];
    float* out        = (float*)d_out;
    float* out_spix   = out;                       // (4,256,64)
    float* out_labels = out + Bn*NSPIX*Cn;         // (4,262144)

    cudaFuncSetAttribute(ssn_iter_kernel,
                         cudaFuncAttributeMaxDynamicSharedMemorySize, SMEM_BYTES);

    init_kernel<<<dim3(NSPIX, Bn), 256>>>(f);
    for (int it = 0; it < 5; it++) {
        ssn_iter_kernel<<<dim3(4, NSPIX, Bn), 256, SMEM_BYTES>>>(
            f, out_labels, it, it == 4);
        update_kernel<<<256, 256>>>(out_spix, it, it == 4);
    }
}

// round 4
// speedup vs baseline: 1.4144x; 1.4144x over previous
#include <cuda_runtime.h>
#include <cstddef>

#define Bn     4
#define Cn     64
#define Hn     512
#define Wn     512
#define NSPIX  256
#define HW     (Hn*Wn)

typedef unsigned long long ull;

// scratch
__device__ float g_spix [Bn*NSPIX*Cn];
__device__ float g_numer[Bn*NSPIX*Cn];
__device__ float g_denom2[2][Bn*NSPIX];

// ---- packed fp32x2 helpers ----
__device__ __forceinline__ ull f2_pack(float a, float b) {
    ull r; asm("mov.b64 %0, {%1,%2};" : "=l"(r) : "f"(a), "f"(b)); return r;
}
__device__ __forceinline__ void f2_unpack(ull v, float& a, float& b) {
    asm("mov.b64 {%0,%1}, %2;" : "=f"(a), "=f"(b) : "l"(v));
}
__device__ __forceinline__ void ffma2(ull& d, ull a, ull b) {
    asm("fma.rn.f32x2 %0, %1, %2, %0;" : "+l"(d) : "l"(a), "l"(b));
}
__device__ __forceinline__ void fadd2(ull& d, ull a) {
    asm("add.rn.f32x2 %0, %0, %1;" : "+l"(d) : "l"(a));
}

// shared layout (float offsets)
#define OFF_G    0                      // [9][64]
#define OFF_GSQ  576                    // [16]
#define OFF_DRED 592                    // [9][8]
#define OFF_W    664                    // [9][264] transposed scalar weights
#define OFF_F    3040                   // [32 cpair][259 px][2]  (16B aligned)
#define SMEM_FLOATS (3040 + 32*259*2)   // 19616 floats = 78.5KB
#define SMEM_BYTES  (SMEM_FLOATS*4)
#define FWORD(cp,p) (OFF_F + ((cp)*259 + (p))*2)
// phase-2 partial overlay (reuses f region after all reads complete)
#define PROW 290                        // ull stride per group row (16 rows x 290 <= f region)

// ---------------------------------------------------------------------------
__global__ void init_kernel(const float* __restrict__ f)
{
    __shared__ float sm[256];
    const int s = blockIdx.x, b = blockIdx.y;
    const int tid = threadIdx.x;
    const int c = tid & 63, part = tid >> 6;
    const int R = s >> 4, Cc = s & 15;
    const int y0 = R*32 + part*8, x0 = Cc*32;
    const float* fp = f + ((size_t)(b*Cn + c))*HW + (size_t)y0*Wn + x0;

    float sum = 0.f;
    for (int yy = 0; yy < 8; yy++) {
        const float4* r = (const float4*)(fp + (size_t)yy*Wn);
        #pragma unroll
        for (int x4 = 0; x4 < 8; x4++) {
            float4 v = r[x4];
            sum += (v.x + v.y) + (v.z + v.w);
        }
    }
    sm[tid] = sum;

    int gid = ((blockIdx.y*gridDim.x) + blockIdx.x)*256 + tid;
    if (gid < Bn*NSPIX*Cn) g_numer[gid] = 0.f;
    if (gid < 2*Bn*NSPIX)  ((float*)g_denom2)[gid] = 0.f;

    __syncthreads();
    if (tid < 64) {
        float t = sm[tid] + sm[64+tid] + sm[128+tid] + sm[192+tid];
        g_spix[(b*NSPIX + s)*Cn + tid] = t * (1.0f/1024.0f);
    }
}

// ---------------------------------------------------------------------------
// fused iteration kernel.  grid=(4,256,4)  block=256 (8x32 pixel tile)
// ---------------------------------------------------------------------------
__global__ __launch_bounds__(256, 2)
void ssn_iter_kernel(const float* __restrict__ f,
                     float* __restrict__ out_labels,
                     int it, int last)
{
    extern __shared__ float sm[];
    const int tid = threadIdx.x;
    const int bb = blockIdx.z, cell = blockIdx.y, q = blockIdx.x;
    const int R = cell >> 4, Cc = cell & 15;
    const int y0 = R*32 + q*8, x0 = Cc*32;
    const int par = it & 1;

    int  nbr[9];
    bool valid[9];
    #pragma unroll
    for (int k = 0; k < 9; k++) {
        int rr = R + k/3 - 1, cc = Cc + (k%3) - 1;
        bool v = (rr >= 0) & (rr < 16) & (cc >= 0) & (cc < 16);
        valid[k] = v;
        nbr[k]   = v ? rr*16 + cc : 0;
    }

    // stage g (zero-filled invalid), zero dred
    for (int idx = tid; idx < 576; idx += 256) {
        int k = idx >> 6;
        sm[OFF_G + idx] = valid[k] ? g_spix[(bb*NSPIX + nbr[k])*Cn + (idx & 63)] : 0.f;
    }
    if (tid < 72) sm[OFF_DRED + tid] = 0.f;
    __syncthreads();

    if (tid < 9) {                       // ||g||^2
        float s = 0.f;
        #pragma unroll 8
        for (int c = 0; c < 64; c++) { float gv = sm[OFF_G + tid*64 + c]; s += gv*gv; }
        sm[OFF_GSQ + tid] = s;
    }

    // ---- phase 1: stream f from HBM; stage packed pairs; accumulate dots
    const int p = tid;
    ull acc[9], sv = 0ull;
    #pragma unroll
    for (int k = 0; k < 9; k++) acc[k] = 0ull;
    {
        const float* fp = f + ((size_t)bb*Cn)*HW
                            + (size_t)(y0 + (p >> 5))*Wn + (x0 + (p & 31));
        #pragma unroll 4
        for (int cs = 0; cs < 16; cs++) {
            const int c = cs*4;
            float v0 = fp[(size_t)(c+0)*HW];
            float v1 = fp[(size_t)(c+1)*HW];
            float v2 = fp[(size_t)(c+2)*HW];
            float v3 = fp[(size_t)(c+3)*HW];
            ull p01 = f2_pack(v0, v1);
            ull p23 = f2_pack(v2, v3);
            *(ull*)&sm[FWORD((c>>1),   p)] = p01;
            *(ull*)&sm[FWORD((c>>1)+1, p)] = p23;
            ffma2(sv, p01, p01);
            ffma2(sv, p23, p23);
            #pragma unroll
            for (int k = 0; k < 9; k++) {
                ulonglong2 g2 = *(const ulonglong2*)&sm[OFF_G + k*64 + c];
                ffma2(acc[k], p01, g2.x);
                ffma2(acc[k], p23, g2.y);
            }
        }
    }
    __syncthreads();   // gsq ready; f tile complete

    // ---- softmax per pixel (registers)
    float w[9];
    {
        float sa, sb; f2_unpack(sv, sa, sb);
        const float sv_s = sa + sb;
        float dmin = 3.0e38f;
        #pragma unroll
        for (int k = 0; k < 9; k++) {
            float a, b; f2_unpack(acc[k], a, b);
            float d = valid[k] ? (sv_s - 2.f*(a+b) + sm[OFF_GSQ + k]) : 3.0e38f;
            w[k] = d;
            dmin = fminf(dmin, d);
        }
        if (last) {
            int kb = 0; float bd = w[0];
            #pragma unroll
            for (int k = 1; k < 9; k++) if (w[k] < bd) { bd = w[k]; kb = k; }
            out_labels[(size_t)bb*HW + (size_t)(y0 + (p>>5))*Wn + (x0 + (p&31))]
                = (float)nbr[kb];
        }
        float s = 0.f;
        #pragma unroll
        for (int k = 0; k < 9; k++) { float e = __expf(dmin - w[k]); w[k] = e; s += e; }
        float inv = 1.f / s;
        #pragma unroll
        for (int k = 0; k < 9; k++) w[k] *= inv;
    }

    // transposed scalar weight store (conflict-free STS.32)
    #pragma unroll
    for (int k = 0; k < 9; k++) sm[OFF_W + k*264 + p] = w[k];

    // denominators: 9 block-wide sums
    #pragma unroll
    for (int k = 0; k < 9; k++) {
        float s = w[k];
        s += __shfl_down_sync(0xffffffffu, s, 16);
        s += __shfl_down_sync(0xffffffffu, s, 8);
        s += __shfl_down_sync(0xffffffffu, s, 4);
        s += __shfl_down_sync(0xffffffffu, s, 2);
        s += __shfl_down_sync(0xffffffffu, s, 1);
        if ((tid & 31) == 0) sm[OFF_DRED + k*8 + (tid >> 5)] = s;
    }
    __syncthreads();   // w + dred visible
    if (tid < 9 && valid[tid]) {
        const float* dr = &sm[OFF_DRED + tid*8];
        float s = ((dr[0]+dr[1]) + (dr[2]+dr[3])) + ((dr[4]+dr[5]) + (dr[6]+dr[7]));
        atomicAdd(&g_denom2[par][bb*NSPIX + nbr[tid]], s);
    }

    // ---- phase 2: register partials, NO shared atomics
    const int cp  = tid & 15;            // owns cpairs cp, cp+16
    const int grp = tid >> 4;            // owns pixels grp*16 .. +15
    ull m[18];
    #pragma unroll
    for (int k = 0; k < 18; k++) m[k] = 0ull;
    #pragma unroll 2
    for (int j = 0; j < 16; j++) {
        const int pp = grp*16 + j;
        ull f0 = *(const ull*)&sm[FWORD(cp,      pp)];
        ull f1 = *(const ull*)&sm[FWORD(cp + 16, pp)];
        #pragma unroll
        for (int k = 0; k < 9; k++) {
            float wk = sm[OFF_W + k*264 + pp];     // half-warp broadcast
            ull w2 = f2_pack(wk, wk);
            ffma2(m[k],     w2, f0);
            ffma2(m[k + 9], w2, f1);
        }
    }
    __syncthreads();   // all f reads done -> safe to overlay partials on f region

    {   // write partials: row per group, slot = e*16+cp  (conflict-free STS.64)
        ull* part = (ull*)&sm[OFF_F];
        #pragma unroll
        for (int e = 0; e < 18; e++)
            part[(size_t)grp*PROW + e*16 + cp] = m[e];
    }
    __syncthreads();

    {   // reduce 16 group-partials per slot, then global RED.ADD
        const ull* part = (const ull*)&sm[OFF_F];
        for (int s = tid; s < 288; s += 256) {
            ull sum = part[s];
            #pragma unroll
            for (int g = 1; g < 16; g++) fadd2(sum, part[(size_t)g*PROW + s]);
            int e   = s >> 4;
            int cpi = s & 15;
            int k      = (e < 9) ? e : e - 9;
            int cpair  = (e < 9) ? cpi : cpi + 16;
            float a, b; f2_unpack(sum, a, b);
            float* dst = &g_numer[(bb*NSPIX + nbr[k])*Cn + 2*cpair];
            atomicAdd(dst,     a);     // invalid k contributes exact 0.0
            atomicAdd(dst + 1, b);
        }
    }
}

// ---------------------------------------------------------------------------
__global__ void update_kernel(float* __restrict__ out_spix, int it, int last)
{
    int idx = blockIdx.x*256 + threadIdx.x;     // 65536
    int par = it & 1;
    float val = g_numer[idx] / (g_denom2[par][idx >> 6] + 1e-16f);
    g_spix[idx] = val;
    if (last) out_spix[idx] = val;
    g_numer[idx] = 0.f;
    if (idx < Bn*NSPIX) g_denom2[1 - par][idx] = 0.f;
}

// ---------------------------------------------------------------------------
extern "C" void kernel_launch(void* const* d_in, const int* in_sizes, int n_in,
                              void* d_out, int out_size)
{
    const float* f = (const float*)d_in[0];
    float* out        = (float*)d_out;
    float* out_spix   = out;                       // (4,256,64)
    float* out_labels = out + Bn*NSPIX*Cn;         // (4,262144)

    cudaFuncSetAttribute(ssn_iter_kernel,
                         cudaFuncAttributeMaxDynamicSharedMemorySize, SMEM_BYTES);

    init_kernel<<<dim3(NSPIX, Bn), 256>>>(f);
    for (int it = 0; it < 5; it++) {
        ssn_iter_kernel<<<dim3(4, NSPIX, Bn), 256, SMEM_BYTES>>>(
            f, out_labels, it, it == 4);
        update_kernel<<<256, 256>>>(out_spix, it, it == 4);
    }
}